// round 12
// baseline (speedup 1.0000x reference)
#include <cuda_runtime.h>
#include <cuda_fp16.h>
#include <cstdint>
#include <math.h>

#define N_NODES 40000
#define N_EDGES 640000
#define D 128
#define R 32
#define NB 8

// ---- scratch (static device globals; no runtime allocation) ----
__device__ __half g_xbh[(size_t)N_NODES * NB * D];  // 82 MB: bases 0-7, fp16
__device__ float g_xloop[(size_t)N_NODES * D];      // 20.5 MB: loop block fp32
__device__ float g_s[(size_t)N_NODES * R];          // 5.1 MB
__device__ float g_attdot[(size_t)N_NODES * NB];    // 1.28 MB
__device__ float g_denom[N_NODES];
__device__ float g_accum[(size_t)N_NODES * D];      // 20.5 MB
__device__ float g_colsum[D];
__device__ float g_colsumsq[D];
__device__ float g_scale[D];
__device__ float g_shift[D];
__device__ __half g_xh[(size_t)N_NODES * D];        // x (fp16)
__device__ __half g_wth[9 * D * D];                 // [b][n][k]  (W^T, fp16)
// CSR by src
__device__ int g_cnt[N_NODES];
__device__ int g_cur[N_NODES];
__device__ int g_off[N_NODES + 1];
__device__ int g_pk2[N_EDGES];    // dst*32 + rel, CSR order
__device__ float g_w2[N_EDGES];   // exp(score), CSR order

// ================= fused prep: zero + convert x + convert W + edge histogram =================
__global__ __launch_bounds__(256) void k_prep(const float* __restrict__ x,
                                              const float* __restrict__ w_bases,
                                              const float* __restrict__ w_loop,
                                              const int* __restrict__ src) {
    int idx0 = blockIdx.x * blockDim.x + threadIdx.x;
    int stride = gridDim.x * blockDim.x;
    for (int i = idx0; i < N_NODES; i += stride) { g_denom[i] = 0.f; g_cnt[i] = 0; }
    // grid-wide visibility of g_cnt zeroing before histogram: use a fence-free
    // trick — zero and histogram touch disjoint work per thread only if ordered.
    // Instead: g_cnt zeroing must complete before atomics. Do it via separate
    // loop ordering within the SAME thread is not enough across threads.
    // => histogram moved to a cooperative trick: count with atomicAdd on
    // g_cur (zeroed last round? no). Safe approach: histogram uses atomicAdd
    // on g_cnt zeroed here; enforce with __threadfence + grid-stride phase
    // split is NOT safe. So: histogram runs in k_scan's producer? Keep it
    // simple and SAFE: histogram stays in this kernel but g_cnt zeroing is
    // done by the FIRST grid-stride loop and all blocks then histogram a
    // disjoint slice. Cross-block race exists (block A may histogram before
    // block B zeroes). Fix: zero g_cnt in k_prep, histogram in k_scan prologue.
    for (int i = idx0; i < N_NODES * D; i += stride) {
        g_accum[i] = 0.f;
        g_xh[i] = __float2half_rn(x[i]);
    }
    for (int i = idx0; i < 9 * D * D; i += stride) {
        int b = i >> 14;
        int rem = i & 16383;
        int n = rem >> 7;
        int k = rem & 127;
        float v = (b < 8) ? w_bases[(b << 14) + k * D + n] : w_loop[k * D + n];
        g_wth[i] = __float2half_rn(v);
    }
    for (int i = idx0; i < N_NODES * NB; i += stride) g_attdot[i] = 0.f;
    if (idx0 < D) { g_colsum[idx0] = 0.f; g_colsumsq[idx0] = 0.f; }
    (void)src;
}

// ---------------- histogram (needs g_cnt zeroed by k_prep) ----------------
__global__ __launch_bounds__(256) void k_hist(const int* __restrict__ src) {
    int e = blockIdx.x * blockDim.x + threadIdx.x;
    if (e >= N_EDGES) return;
    atomicAdd(&g_cnt[src[e]], 1);
}

// ================= mma.sync fp16 GEMM, A-resident, 3 bases per CTA =================
#define PAD 40
#define TILE_H (128 * PAD)
#define TILE_B (TILE_H * 2)
#define SMEM_GEMM (512 + 6 * TILE_B)

__device__ __forceinline__ void cpa16(uint32_t dst, const void* src, int sz) {
    asm volatile("cp.async.ca.shared.global [%0], [%1], 16, %2;"
                 :: "r"(dst), "l"(src), "r"(sz));
}

__global__ __launch_bounds__(256, 2) void k_gemm_mma(const float* __restrict__ att) {
    extern __shared__ __align__(16) char dsm[];
    float* atts = (float*)dsm;
    __half* tiles = (__half*)(dsm + 512);

    const int tid = threadIdx.x;
    const int lane = tid & 31;
    const int wid = tid >> 5;
    const int wm = wid & 3;
    const int wn = wid >> 2;
    const int m0 = blockIdx.x * 128;
    const int bgrp = blockIdx.y;

    if (tid < 128) atts[tid] = att[tid];

    const int fi_row[2] = { (0 * 256 + tid) >> 2, (1 * 256 + tid) >> 2 };
    const int fi_c8[2]  = { ((0 * 256 + tid) & 3) * 8, ((1 * 256 + tid) & 3) * 8 };

#pragma unroll
    for (int kc = 0; kc < 4; kc++) {
        __half* Ahi = tiles + kc * TILE_H;
#pragma unroll
        for (int l = 0; l < 2; l++) {
            int row = fi_row[l], c8 = fi_c8[l];
            int g = m0 + row;
            bool ok = g < N_NODES;
            int gc = ok ? g : 0;
            int sz = ok ? 16 : 0;
            cpa16((uint32_t)__cvta_generic_to_shared(Ahi + row * PAD + c8),
                  g_xh + (size_t)gc * D + kc * 32 + c8, sz);
        }
    }
    asm volatile("cp.async.commit_group;" ::: "memory");

#define ISSUE_B(jj, s) do {                                                       \
    const int _b = bgrp * 3 + ((jj) >> 2);                                        \
    const int _k0 = ((jj) & 3) * 32;                                              \
    const __half* _Bg = g_wth + _b * (D * D);                                     \
    __half* _Bs = tiles + (4 + (s)) * TILE_H;                                     \
    _Pragma("unroll")                                                             \
    for (int _l = 0; _l < 2; _l++) {                                              \
        int _row = fi_row[_l], _c8 = fi_c8[_l];                                   \
        cpa16((uint32_t)__cvta_generic_to_shared(_Bs + _row * PAD + _c8),         \
              _Bg + _row * D + _k0 + _c8, 16);                                    \
    }                                                                             \
    asm volatile("cp.async.commit_group;" ::: "memory");                          \
} while (0)

    ISSUE_B(0, 0);

    const int a_row = wm * 32 + (lane & 15);
    const int a_cb = (lane >> 4) << 3;
    const int b_row = wn * 64 + (lane & 7) + ((lane >> 4) << 3);
    const int b_cb = (lane & 8);

    float acc[2][8][4];

#pragma unroll 1
    for (int j = 0; j < 12; j++) {
        const int kc = j & 3;
        const int s = j & 1;
        __syncthreads();
        if (j < 11) {
            ISSUE_B(j + 1, s ^ 1);
            asm volatile("cp.async.wait_group 1;" ::: "memory");
        } else {
            asm volatile("cp.async.wait_group 0;" ::: "memory");
        }
        __syncthreads();

        if (kc == 0) {
#pragma unroll
            for (int mf = 0; mf < 2; mf++)
#pragma unroll
                for (int nf = 0; nf < 8; nf++)
#pragma unroll
                    for (int r = 0; r < 4; r++) acc[mf][nf][r] = 0.f;
        }

        const __half* Ah = tiles + kc * TILE_H;
        const __half* Bh = tiles + (4 + s) * TILE_H;

#pragma unroll
        for (int ks = 0; ks < 2; ks++) {
            const int kk = ks * 16;
            uint32_t ah[2][4], bh[8][2];
#pragma unroll
            for (int mf = 0; mf < 2; mf++) {
                uint32_t addr = (uint32_t)__cvta_generic_to_shared(
                    Ah + (a_row + mf * 16) * PAD + kk + a_cb);
                asm volatile("ldmatrix.sync.aligned.m8n8.x4.shared.b16 {%0,%1,%2,%3}, [%4];"
                    : "=r"(ah[mf][0]), "=r"(ah[mf][1]), "=r"(ah[mf][2]), "=r"(ah[mf][3])
                    : "r"(addr));
            }
#pragma unroll
            for (int nf2 = 0; nf2 < 4; nf2++) {
                uint32_t addr = (uint32_t)__cvta_generic_to_shared(
                    Bh + (b_row + nf2 * 16) * PAD + kk + b_cb);
                asm volatile("ldmatrix.sync.aligned.m8n8.x4.shared.b16 {%0,%1,%2,%3}, [%4];"
                    : "=r"(bh[nf2 * 2][0]), "=r"(bh[nf2 * 2][1]),
                      "=r"(bh[nf2 * 2 + 1][0]), "=r"(bh[nf2 * 2 + 1][1])
                    : "r"(addr));
            }
#define MMA(ar, br) \
    asm volatile("mma.sync.aligned.m16n8k16.row.col.f32.f16.f16.f32 " \
        "{%0,%1,%2,%3}, {%4,%5,%6,%7}, {%8,%9}, {%0,%1,%2,%3};" \
        : "+f"(acc[mf][nf][0]), "+f"(acc[mf][nf][1]), \
          "+f"(acc[mf][nf][2]), "+f"(acc[mf][nf][3]) \
        : "r"((ar)[0]), "r"((ar)[1]), "r"((ar)[2]), "r"((ar)[3]), \
          "r"((br)[0]), "r"((br)[1]))
#pragma unroll
            for (int mf = 0; mf < 2; mf++)
#pragma unroll
                for (int nf = 0; nf < 8; nf++) MMA(ah[mf], bh[nf]);
#undef MMA
        }

        if (kc == 3) {
            const int b = bgrp * 3 + (j >> 2);
            if (b < 8) {
#pragma unroll
                for (int mf = 0; mf < 2; mf++) {
                    int r1 = m0 + wm * 32 + mf * 16 + (lane >> 2);
                    int r2 = r1 + 8;
#pragma unroll
                    for (int nf = 0; nf < 8; nf++) {
                        int col = wn * 64 + nf * 8 + (lane & 3) * 2;
                        if (r1 < N_NODES)
                            *(__half2*)(g_xbh + (size_t)r1 * (NB * D) + b * D + col) =
                                __floats2half2_rn(acc[mf][nf][0], acc[mf][nf][1]);
                        if (r2 < N_NODES)
                            *(__half2*)(g_xbh + (size_t)r2 * (NB * D) + b * D + col) =
                                __floats2half2_rn(acc[mf][nf][2], acc[mf][nf][3]);
                    }
                }
                float ad[4] = {0.f, 0.f, 0.f, 0.f};
#pragma unroll
                for (int mf = 0; mf < 2; mf++)
#pragma unroll
                    for (int nf = 0; nf < 8; nf++) {
                        int col = wn * 64 + nf * 8 + (lane & 3) * 2;
                        float a0 = atts[col], a1 = atts[col + 1];
                        ad[mf * 2 + 0] = fmaf(a0, acc[mf][nf][0], fmaf(a1, acc[mf][nf][1], ad[mf * 2 + 0]));
                        ad[mf * 2 + 1] = fmaf(a0, acc[mf][nf][2], fmaf(a1, acc[mf][nf][3], ad[mf * 2 + 1]));
                    }
#pragma unroll
                for (int off = 1; off <= 2; off <<= 1)
#pragma unroll
                    for (int q = 0; q < 4; q++) ad[q] += __shfl_xor_sync(0xffffffffu, ad[q], off);
                if ((lane & 3) == 0) {
                    int rbase = m0 + wm * 32 + (lane >> 2);
#pragma unroll
                    for (int mf = 0; mf < 2; mf++) {
                        int g1 = rbase + mf * 16;
                        if (g1 < N_NODES) atomicAdd(&g_attdot[(size_t)g1 * NB + b], ad[mf * 2 + 0]);
                        if (g1 + 8 < N_NODES) atomicAdd(&g_attdot[(size_t)(g1 + 8) * NB + b], ad[mf * 2 + 1]);
                    }
                }
            } else {
#pragma unroll
                for (int mf = 0; mf < 2; mf++) {
                    int r1 = m0 + wm * 32 + mf * 16 + (lane >> 2);
                    int r2 = r1 + 8;
#pragma unroll
                    for (int nf = 0; nf < 8; nf++) {
                        int col = wn * 64 + nf * 8 + (lane & 3) * 2;
                        if (r1 < N_NODES)
                            *(float2*)(g_xloop + (size_t)r1 * D + col) =
                                make_float2(acc[mf][nf][0], acc[mf][nf][1]);
                        if (r2 < N_NODES)
                            *(float2*)(g_xloop + (size_t)r2 * D + col) =
                                make_float2(acc[mf][nf][2], acc[mf][nf][3]);
                    }
                }
            }
        }
    }
}

__global__ __launch_bounds__(1024) void k_scan() {
    __shared__ int ssum[1024];
    const int T = 1024, C = (N_NODES + T - 1) / T;
    int t = threadIdx.x;
    int lo = t * C, hi = min(lo + C, N_NODES);
    int s = 0;
    for (int i = lo; i < hi; i++) s += g_cnt[i];
    ssum[t] = s;
    __syncthreads();
    for (int off = 1; off < T; off <<= 1) {
        int u = (t >= off) ? ssum[t - off] : 0;
        __syncthreads();
        ssum[t] += u;
        __syncthreads();
    }
    int run = ssum[t] - s;
    for (int i = lo; i < hi; i++) {
        g_off[i] = run;
        g_cur[i] = run;
        run += g_cnt[i];
    }
    if (t == 0) g_off[N_NODES] = N_EDGES;
}

__global__ __launch_bounds__(256) void k_s2(const float* __restrict__ coef) {
    int t = blockIdx.x * blockDim.x + threadIdx.x;
    int node = t >> 5;
    int r = t & 31;
    if (node >= N_NODES) return;
    const float* ad = g_attdot + (size_t)node * NB;
    float s = 0.f;
#pragma unroll
    for (int b = 0; b < NB; b++) s = fmaf(coef[r * NB + b], ad[b], s);
    g_s[(size_t)node * R + r] = s;
}

// ---------------- fused scatter + score ----------------
__global__ __launch_bounds__(256) void k_scatter(const int* __restrict__ src,
                                                 const int* __restrict__ dst,
                                                 const int* __restrict__ rel) {
    int e = blockIdx.x * blockDim.x + threadIdx.x;
    if (e >= N_EDGES) return;
    int sN = src[e], dN = dst[e], rr = rel[e];
    float sc = g_s[(size_t)sN * R + rr] + g_s[(size_t)dN * R + rr];
    sc = (sc >= 0.f) ? sc : 0.01f * sc;
    float ez = expf(sc);
    int pos = atomicAdd(&g_cur[sN], 1);
    g_pk2[pos] = dN * 32 + rr;
    g_w2[pos] = ez;
    atomicAdd(&g_denom[dN], ez);
}

// ---------------- edge pass 2: unnormalized accumulate (denom folded out) ----------------
__global__ __launch_bounds__(256) void k_edge2(const float* __restrict__ coef) {
    int n = (blockIdx.x * blockDim.x + threadIdx.x) >> 5;
    int lane = threadIdx.x & 31;
    if (n >= N_NODES) return;
    int beg = g_off[n], end = g_off[n + 1];
    if (beg == end) return;
    const uint2* xp = (const uint2*)(g_xbh + (size_t)n * (NB * D)) + lane;
    float f[NB][4];
#pragma unroll
    for (int b = 0; b < NB; b++) {
        uint2 u = xp[b * 32];
        float2 f0 = __half22float2(*(const __half2*)&u.x);
        float2 f1 = __half22float2(*(const __half2*)&u.y);
        f[b][0] = f0.x; f[b][1] = f0.y; f[b][2] = f1.x; f[b][3] = f1.y;
    }
#pragma unroll 2
    for (int j = beg; j < end; j++) {
        int pk = g_pk2[j];
        float w = g_w2[j];          // raw exp(score); normalization folded into k_ft/k_out
        int dN = pk >> 5, rr = pk & 31;
        const float4* cp = (const float4*)(coef + rr * NB);
        float4 c0 = cp[0], c1 = cp[1];
        float4 acc;
        acc.x = c0.x * f[0][0]; acc.y = c0.x * f[0][1]; acc.z = c0.x * f[0][2]; acc.w = c0.x * f[0][3];
        acc.x = fmaf(c0.y, f[1][0], acc.x); acc.y = fmaf(c0.y, f[1][1], acc.y);
        acc.z = fmaf(c0.y, f[1][2], acc.z); acc.w = fmaf(c0.y, f[1][3], acc.w);
        acc.x = fmaf(c0.z, f[2][0], acc.x); acc.y = fmaf(c0.z, f[2][1], acc.y);
        acc.z = fmaf(c0.z, f[2][2], acc.z); acc.w = fmaf(c0.z, f[2][3], acc.w);
        acc.x = fmaf(c0.w, f[3][0], acc.x); acc.y = fmaf(c0.w, f[3][1], acc.y);
        acc.z = fmaf(c0.w, f[3][2], acc.z); acc.w = fmaf(c0.w, f[3][3], acc.w);
        acc.x = fmaf(c1.x, f[4][0], acc.x); acc.y = fmaf(c1.x, f[4][1], acc.y);
        acc.z = fmaf(c1.x, f[4][2], acc.z); acc.w = fmaf(c1.x, f[4][3], acc.w);
        acc.x = fmaf(c1.y, f[5][0], acc.x); acc.y = fmaf(c1.y, f[5][1], acc.y);
        acc.z = fmaf(c1.y, f[5][2], acc.z); acc.w = fmaf(c1.y, f[5][3], acc.w);
        acc.x = fmaf(c1.z, f[6][0], acc.x); acc.y = fmaf(c1.z, f[6][1], acc.y);
        acc.z = fmaf(c1.z, f[6][2], acc.z); acc.w = fmaf(c1.z, f[6][3], acc.w);
        acc.x = fmaf(c1.w, f[7][0], acc.x); acc.y = fmaf(c1.w, f[7][1], acc.y);
        acc.z = fmaf(c1.w, f[7][2], acc.z); acc.w = fmaf(c1.w, f[7][3], acc.w);
        acc.x *= w; acc.y *= w; acc.z *= w; acc.w *= w;
        atomicAdd((float4*)(g_accum + (size_t)dN * D + lane * 4), acc);
    }
}

// ---------------- column stats (normalization applied here) ----------------
__global__ __launch_bounds__(128) void k_ft(const float* __restrict__ norm) {
    int o = threadIdx.x;
    float lsum = 0.f, lsq = 0.f;
    for (int n = blockIdx.x; n < N_NODES; n += gridDim.x) {
        float dn = g_denom[n];
        float rn = norm[n] / (dn > 0.f ? dn : 1.f);
        float v = g_accum[(size_t)n * D + o] * rn + g_xloop[(size_t)n * D + o];
        lsum += v;
        lsq += v * v;
    }
    atomicAdd(&g_colsum[o], lsum);
    atomicAdd(&g_colsumsq[o], lsq);
}

__global__ void k_bn(const float* __restrict__ gamma, const float* __restrict__ beta) {
    int o = threadIdx.x;
    float mu = g_colsum[o] / (float)N_NODES;
    float var = g_colsumsq[o] / (float)N_NODES - mu * mu;
    float inv = rsqrtf(var + 1e-5f);
    float sc = gamma[o] * inv;
    g_scale[o] = sc;
    g_shift[o] = beta[o] - mu * sc;
}

__global__ __launch_bounds__(256) void k_out(const float* __restrict__ norm,
                                             float* __restrict__ out) {
    int i = blockIdx.x * blockDim.x + threadIdx.x;
    int total = N_NODES * D / 4;
    if (i >= total) return;
    int n = (i * 4) >> 7;
    float dn = g_denom[n];
    float rn = norm[n] / (dn > 0.f ? dn : 1.f);
    float4 a = ((const float4*)g_accum)[i];
    float4 xl = ((const float4*)g_xloop)[i];
    int o = (i * 4) & (D - 1);
    float4 r;
    r.x = fmaxf(0.f, (a.x * rn + xl.x) * g_scale[o + 0] + g_shift[o + 0]);
    r.y = fmaxf(0.f, (a.y * rn + xl.y) * g_scale[o + 1] + g_shift[o + 1]);
    r.z = fmaxf(0.f, (a.z * rn + xl.z) * g_scale[o + 2] + g_shift[o + 2]);
    r.w = fmaxf(0.f, (a.w * rn + xl.w) * g_scale[o + 3] + g_shift[o + 3]);
    ((float4*)out)[i] = r;
}

extern "C" void kernel_launch(void* const* d_in, const int* in_sizes, int n_in,
                              void* d_out, int out_size) {
    const float* x       = (const float*)d_in[0];
    const float* norm    = (const float*)d_in[1];
    const int*   esrc    = (const int*)d_in[2];
    const int*   edst    = (const int*)d_in[3];
    const int*   erel    = (const int*)d_in[4];
    const float* w_loop  = (const float*)d_in[5];
    const float* w_bases = (const float*)d_in[6];
    const float* coef    = (const float*)d_in[7];
    const float* att     = (const float*)d_in[8];
    const float* gamma   = (const float*)d_in[10];
    const float* beta    = (const float*)d_in[11];
    float* out = (float*)d_out;

    cudaFuncSetAttribute(k_gemm_mma, cudaFuncAttributeMaxDynamicSharedMemorySize, SMEM_GEMM);

    k_prep<<<2048, 256>>>(x, w_bases, w_loop, esrc);
    k_hist<<<(N_EDGES + 255) / 256, 256>>>(esrc);
    k_scan<<<1, 1024>>>();

    dim3 gg((N_NODES + 127) / 128, 3);
    k_gemm_mma<<<gg, 256, SMEM_GEMM>>>(att);

    k_s2<<<(N_NODES * 32 + 255) / 256, 256>>>(coef);
    k_scatter<<<(N_EDGES + 255) / 256, 256>>>(esrc, edst, erel);
    k_edge2<<<(N_NODES * 32 + 255) / 256, 256>>>(coef);
    k_ft<<<512, 128>>>(norm);
    k_bn<<<1, 128>>>(gamma, beta);
    k_out<<<(N_NODES * D / 4 + 255) / 256, 256>>>(norm, out);
}

// round 13
// speedup vs baseline: 1.0146x; 1.0146x over previous
#include <cuda_runtime.h>
#include <cuda_fp16.h>
#include <cstdint>
#include <math.h>

#define N_NODES 40000
#define N_EDGES 640000
#define D 128
#define R 32
#define NB 8

// ---- scratch (static device globals; no runtime allocation) ----
__device__ __half g_xbh[(size_t)N_NODES * NB * D];  // 82 MB: bases 0-7, fp16
__device__ float g_xloop[(size_t)N_NODES * D];      // 20.5 MB: loop block fp32
__device__ float g_s[(size_t)N_NODES * R];          // 5.1 MB
__device__ float g_attdot[(size_t)N_NODES * NB];    // 1.28 MB
__device__ float g_denom[N_NODES];
__device__ float g_accum[(size_t)N_NODES * D];      // 20.5 MB
__device__ float g_colsum[D];
__device__ float g_colsumsq[D];
__device__ float g_scale[D];
__device__ float g_shift[D];
__device__ __half g_xh[(size_t)N_NODES * D];        // x (fp16)
__device__ __half g_wth[9 * D * D];                 // [b][n][k]  (W^T, fp16)
// CSR by src
__device__ int g_cnt[N_NODES];
__device__ int g_cur[N_NODES];
__device__ int g_off[N_NODES + 1];
__device__ int g_pk2[N_EDGES];    // dst*32 + rel, CSR order
__device__ float g_w2[N_EDGES];   // exp(score), CSR order

// ================= fused prep: zero + convert x + convert W =================
__global__ __launch_bounds__(256) void k_prep(const float* __restrict__ x,
                                              const float* __restrict__ w_bases,
                                              const float* __restrict__ w_loop) {
    int idx0 = blockIdx.x * blockDim.x + threadIdx.x;
    int stride = gridDim.x * blockDim.x;
    for (int i = idx0; i < N_NODES * D; i += stride) {
        g_accum[i] = 0.f;
        g_xh[i] = __float2half_rn(x[i]);
    }
    for (int i = idx0; i < 9 * D * D; i += stride) {
        int b = i >> 14;
        int rem = i & 16383;
        int n = rem >> 7;
        int k = rem & 127;
        float v = (b < 8) ? w_bases[(b << 14) + k * D + n] : w_loop[k * D + n];
        g_wth[i] = __float2half_rn(v);
    }
    for (int i = idx0; i < N_NODES * NB; i += stride) g_attdot[i] = 0.f;
    for (int i = idx0; i < N_NODES; i += stride) { g_denom[i] = 0.f; g_cnt[i] = 0; }
    if (idx0 < D) { g_colsum[idx0] = 0.f; g_colsumsq[idx0] = 0.f; }
}

// ---------------- histogram ----------------
__global__ __launch_bounds__(256) void k_hist(const int* __restrict__ src) {
    int e = blockIdx.x * blockDim.x + threadIdx.x;
    if (e >= N_EDGES) return;
    atomicAdd(&g_cnt[src[e]], 1);
}

// ================= mma.sync fp16 GEMM, A-resident, 3 bases per CTA =================
// Single-sync pipeline: wait_group 0 -> sync -> issue next B -> compute.
#define PAD 40
#define TILE_H (128 * PAD)
#define TILE_B (TILE_H * 2)
#define SMEM_GEMM (512 + 6 * TILE_B)

__device__ __forceinline__ void cpa16(uint32_t dst, const void* src, int sz) {
    asm volatile("cp.async.ca.shared.global [%0], [%1], 16, %2;"
                 :: "r"(dst), "l"(src), "r"(sz));
}

__global__ __launch_bounds__(256, 2) void k_gemm_mma(const float* __restrict__ att) {
    extern __shared__ __align__(16) char dsm[];
    float* atts = (float*)dsm;
    __half* tiles = (__half*)(dsm + 512);

    const int tid = threadIdx.x;
    const int lane = tid & 31;
    const int wid = tid >> 5;
    const int wm = wid & 3;
    const int wn = wid >> 2;
    const int m0 = blockIdx.x * 128;
    const int bgrp = blockIdx.y;

    if (tid < 128) atts[tid] = att[tid];

    const int fi_row[2] = { (0 * 256 + tid) >> 2, (1 * 256 + tid) >> 2 };
    const int fi_c8[2]  = { ((0 * 256 + tid) & 3) * 8, ((1 * 256 + tid) & 3) * 8 };

    // ---- load all A tiles (4 kc) ----
#pragma unroll
    for (int kc = 0; kc < 4; kc++) {
        __half* Ahi = tiles + kc * TILE_H;
#pragma unroll
        for (int l = 0; l < 2; l++) {
            int row = fi_row[l], c8 = fi_c8[l];
            int g = m0 + row;
            bool ok = g < N_NODES;
            int gc = ok ? g : 0;
            int sz = ok ? 16 : 0;
            cpa16((uint32_t)__cvta_generic_to_shared(Ahi + row * PAD + c8),
                  g_xh + (size_t)gc * D + kc * 32 + c8, sz);
        }
    }

#define ISSUE_B(jj, s) do {                                                       \
    const int _b = bgrp * 3 + ((jj) >> 2);                                        \
    const int _k0 = ((jj) & 3) * 32;                                              \
    const __half* _Bg = g_wth + _b * (D * D);                                     \
    __half* _Bs = tiles + (4 + (s)) * TILE_H;                                     \
    _Pragma("unroll")                                                             \
    for (int _l = 0; _l < 2; _l++) {                                              \
        int _row = fi_row[_l], _c8 = fi_c8[_l];                                   \
        cpa16((uint32_t)__cvta_generic_to_shared(_Bs + _row * PAD + _c8),         \
              _Bg + _row * D + _k0 + _c8, 16);                                    \
    }                                                                             \
    asm volatile("cp.async.commit_group;" ::: "memory");                          \
} while (0)

    ISSUE_B(0, 0);   // commits A tiles + B(0) in one group

    const int a_row = wm * 32 + (lane & 15);
    const int a_cb = (lane >> 4) << 3;
    const int b_row = wn * 64 + (lane & 7) + ((lane >> 4) << 3);
    const int b_cb = (lane & 8);

    float acc[2][8][4];

#pragma unroll 1
    for (int j = 0; j < 12; j++) {
        const int kc = j & 3;
        const int s = j & 1;
        // my outstanding copies (incl. B(j)) have landed:
        asm volatile("cp.async.wait_group 0;" ::: "memory");
        // all threads' copies landed AND all threads finished consuming s^1:
        __syncthreads();
        if (j < 11) ISSUE_B(j + 1, s ^ 1);

        if (kc == 0) {
#pragma unroll
            for (int mf = 0; mf < 2; mf++)
#pragma unroll
                for (int nf = 0; nf < 8; nf++)
#pragma unroll
                    for (int r = 0; r < 4; r++) acc[mf][nf][r] = 0.f;
        }

        const __half* Ah = tiles + kc * TILE_H;
        const __half* Bh = tiles + (4 + s) * TILE_H;

#pragma unroll
        for (int ks = 0; ks < 2; ks++) {
            const int kk = ks * 16;
            uint32_t ah[2][4], bh[8][2];
#pragma unroll
            for (int mf = 0; mf < 2; mf++) {
                uint32_t addr = (uint32_t)__cvta_generic_to_shared(
                    Ah + (a_row + mf * 16) * PAD + kk + a_cb);
                asm volatile("ldmatrix.sync.aligned.m8n8.x4.shared.b16 {%0,%1,%2,%3}, [%4];"
                    : "=r"(ah[mf][0]), "=r"(ah[mf][1]), "=r"(ah[mf][2]), "=r"(ah[mf][3])
                    : "r"(addr));
            }
#pragma unroll
            for (int nf2 = 0; nf2 < 4; nf2++) {
                uint32_t addr = (uint32_t)__cvta_generic_to_shared(
                    Bh + (b_row + nf2 * 16) * PAD + kk + b_cb);
                asm volatile("ldmatrix.sync.aligned.m8n8.x4.shared.b16 {%0,%1,%2,%3}, [%4];"
                    : "=r"(bh[nf2 * 2][0]), "=r"(bh[nf2 * 2][1]),
                      "=r"(bh[nf2 * 2 + 1][0]), "=r"(bh[nf2 * 2 + 1][1])
                    : "r"(addr));
            }
#define MMA(ar, br) \
    asm volatile("mma.sync.aligned.m16n8k16.row.col.f32.f16.f16.f32 " \
        "{%0,%1,%2,%3}, {%4,%5,%6,%7}, {%8,%9}, {%0,%1,%2,%3};" \
        : "+f"(acc[mf][nf][0]), "+f"(acc[mf][nf][1]), \
          "+f"(acc[mf][nf][2]), "+f"(acc[mf][nf][3]) \
        : "r"((ar)[0]), "r"((ar)[1]), "r"((ar)[2]), "r"((ar)[3]), \
          "r"((br)[0]), "r"((br)[1]))
#pragma unroll
            for (int mf = 0; mf < 2; mf++)
#pragma unroll
                for (int nf = 0; nf < 8; nf++) MMA(ah[mf], bh[nf]);
#undef MMA
        }

        if (kc == 3) {
            const int b = bgrp * 3 + (j >> 2);
            if (b < 8) {
#pragma unroll
                for (int mf = 0; mf < 2; mf++) {
                    int r1 = m0 + wm * 32 + mf * 16 + (lane >> 2);
                    int r2 = r1 + 8;
#pragma unroll
                    for (int nf = 0; nf < 8; nf++) {
                        int col = wn * 64 + nf * 8 + (lane & 3) * 2;
                        if (r1 < N_NODES)
                            *(__half2*)(g_xbh + (size_t)r1 * (NB * D) + b * D + col) =
                                __floats2half2_rn(acc[mf][nf][0], acc[mf][nf][1]);
                        if (r2 < N_NODES)
                            *(__half2*)(g_xbh + (size_t)r2 * (NB * D) + b * D + col) =
                                __floats2half2_rn(acc[mf][nf][2], acc[mf][nf][3]);
                    }
                }
                float ad[4] = {0.f, 0.f, 0.f, 0.f};
#pragma unroll
                for (int mf = 0; mf < 2; mf++)
#pragma unroll
                    for (int nf = 0; nf < 8; nf++) {
                        int col = wn * 64 + nf * 8 + (lane & 3) * 2;
                        float a0 = atts[col], a1 = atts[col + 1];
                        ad[mf * 2 + 0] = fmaf(a0, acc[mf][nf][0], fmaf(a1, acc[mf][nf][1], ad[mf * 2 + 0]));
                        ad[mf * 2 + 1] = fmaf(a0, acc[mf][nf][2], fmaf(a1, acc[mf][nf][3], ad[mf * 2 + 1]));
                    }
#pragma unroll
                for (int off = 1; off <= 2; off <<= 1)
#pragma unroll
                    for (int q = 0; q < 4; q++) ad[q] += __shfl_xor_sync(0xffffffffu, ad[q], off);
                if ((lane & 3) == 0) {
                    int rbase = m0 + wm * 32 + (lane >> 2);
#pragma unroll
                    for (int mf = 0; mf < 2; mf++) {
                        int g1 = rbase + mf * 16;
                        if (g1 < N_NODES) atomicAdd(&g_attdot[(size_t)g1 * NB + b], ad[mf * 2 + 0]);
                        if (g1 + 8 < N_NODES) atomicAdd(&g_attdot[(size_t)(g1 + 8) * NB + b], ad[mf * 2 + 1]);
                    }
                }
            } else {
#pragma unroll
                for (int mf = 0; mf < 2; mf++) {
                    int r1 = m0 + wm * 32 + mf * 16 + (lane >> 2);
                    int r2 = r1 + 8;
#pragma unroll
                    for (int nf = 0; nf < 8; nf++) {
                        int col = wn * 64 + nf * 8 + (lane & 3) * 2;
                        if (r1 < N_NODES)
                            *(float2*)(g_xloop + (size_t)r1 * D + col) =
                                make_float2(acc[mf][nf][0], acc[mf][nf][1]);
                        if (r2 < N_NODES)
                            *(float2*)(g_xloop + (size_t)r2 * D + col) =
                                make_float2(acc[mf][nf][2], acc[mf][nf][3]);
                    }
                }
            }
        }
    }
}

__global__ __launch_bounds__(1024) void k_scan() {
    __shared__ int ssum[1024];
    const int T = 1024, C = (N_NODES + T - 1) / T;
    int t = threadIdx.x;
    int lo = t * C, hi = min(lo + C, N_NODES);
    int s = 0;
    for (int i = lo; i < hi; i++) s += g_cnt[i];
    ssum[t] = s;
    __syncthreads();
    for (int off = 1; off < T; off <<= 1) {
        int u = (t >= off) ? ssum[t - off] : 0;
        __syncthreads();
        ssum[t] += u;
        __syncthreads();
    }
    int run = ssum[t] - s;
    for (int i = lo; i < hi; i++) {
        g_off[i] = run;
        g_cur[i] = run;
        run += g_cnt[i];
    }
    if (t == 0) g_off[N_NODES] = N_EDGES;
}

__global__ __launch_bounds__(256) void k_s2(const float* __restrict__ coef) {
    int t = blockIdx.x * blockDim.x + threadIdx.x;
    int node = t >> 5;
    int r = t & 31;
    if (node >= N_NODES) return;
    const float* ad = g_attdot + (size_t)node * NB;
    float s = 0.f;
#pragma unroll
    for (int b = 0; b < NB; b++) s = fmaf(coef[r * NB + b], ad[b], s);
    g_s[(size_t)node * R + r] = s;
}

// ---------------- fused scatter + score ----------------
__global__ __launch_bounds__(256) void k_scatter(const int* __restrict__ src,
                                                 const int* __restrict__ dst,
                                                 const int* __restrict__ rel) {
    int e = blockIdx.x * blockDim.x + threadIdx.x;
    if (e >= N_EDGES) return;
    int sN = src[e], dN = dst[e], rr = rel[e];
    float sc = g_s[(size_t)sN * R + rr] + g_s[(size_t)dN * R + rr];
    sc = (sc >= 0.f) ? sc : 0.01f * sc;
    float ez = expf(sc);
    int pos = atomicAdd(&g_cur[sN], 1);
    g_pk2[pos] = dN * 32 + rr;
    g_w2[pos] = ez;
    atomicAdd(&g_denom[dN], ez);
}

// ---------------- edge pass 2: CSR by src, warp per node (normalized weight) ----------------
__global__ __launch_bounds__(256) void k_edge2(const float* __restrict__ coef) {
    int n = (blockIdx.x * blockDim.x + threadIdx.x) >> 5;
    int lane = threadIdx.x & 31;
    if (n >= N_NODES) return;
    int beg = g_off[n], end = g_off[n + 1];
    if (beg == end) return;
    const uint2* xp = (const uint2*)(g_xbh + (size_t)n * (NB * D)) + lane;
    float f[NB][4];
#pragma unroll
    for (int b = 0; b < NB; b++) {
        uint2 u = xp[b * 32];
        float2 f0 = __half22float2(*(const __half2*)&u.x);
        float2 f1 = __half22float2(*(const __half2*)&u.y);
        f[b][0] = f0.x; f[b][1] = f0.y; f[b][2] = f1.x; f[b][3] = f1.y;
    }
#pragma unroll 2
    for (int j = beg; j < end; j++) {
        int pk = g_pk2[j];
        float ez = g_w2[j];
        int dN = pk >> 5, rr = pk & 31;
        float w = ez / g_denom[dN];
        const float4* cp = (const float4*)(coef + rr * NB);
        float4 c0 = cp[0], c1 = cp[1];
        float4 acc;
        acc.x = c0.x * f[0][0]; acc.y = c0.x * f[0][1]; acc.z = c0.x * f[0][2]; acc.w = c0.x * f[0][3];
        acc.x = fmaf(c0.y, f[1][0], acc.x); acc.y = fmaf(c0.y, f[1][1], acc.y);
        acc.z = fmaf(c0.y, f[1][2], acc.z); acc.w = fmaf(c0.y, f[1][3], acc.w);
        acc.x = fmaf(c0.z, f[2][0], acc.x); acc.y = fmaf(c0.z, f[2][1], acc.y);
        acc.z = fmaf(c0.z, f[2][2], acc.z); acc.w = fmaf(c0.z, f[2][3], acc.w);
        acc.x = fmaf(c0.w, f[3][0], acc.x); acc.y = fmaf(c0.w, f[3][1], acc.y);
        acc.z = fmaf(c0.w, f[3][2], acc.z); acc.w = fmaf(c0.w, f[3][3], acc.w);
        acc.x = fmaf(c1.x, f[4][0], acc.x); acc.y = fmaf(c1.x, f[4][1], acc.y);
        acc.z = fmaf(c1.x, f[4][2], acc.z); acc.w = fmaf(c1.x, f[4][3], acc.w);
        acc.x = fmaf(c1.y, f[5][0], acc.x); acc.y = fmaf(c1.y, f[5][1], acc.y);
        acc.z = fmaf(c1.y, f[5][2], acc.z); acc.w = fmaf(c1.y, f[5][3], acc.w);
        acc.x = fmaf(c1.z, f[6][0], acc.x); acc.y = fmaf(c1.z, f[6][1], acc.y);
        acc.z = fmaf(c1.z, f[6][2], acc.z); acc.w = fmaf(c1.z, f[6][3], acc.w);
        acc.x = fmaf(c1.w, f[7][0], acc.x); acc.y = fmaf(c1.w, f[7][1], acc.y);
        acc.z = fmaf(c1.w, f[7][2], acc.z); acc.w = fmaf(c1.w, f[7][3], acc.w);
        acc.x *= w; acc.y *= w; acc.z *= w; acc.w *= w;
        atomicAdd((float4*)(g_accum + (size_t)dN * D + lane * 4), acc);
    }
}

// ---------------- column stats ----------------
__global__ __launch_bounds__(128) void k_ft(const float* __restrict__ norm) {
    int o = threadIdx.x;
    float lsum = 0.f, lsq = 0.f;
    for (int n = blockIdx.x; n < N_NODES; n += gridDim.x) {
        float v = g_accum[(size_t)n * D + o] * norm[n] + g_xloop[(size_t)n * D + o];
        lsum += v;
        lsq += v * v;
    }
    atomicAdd(&g_colsum[o], lsum);
    atomicAdd(&g_colsumsq[o], lsq);
}

__global__ void k_bn(const float* __restrict__ gamma, const float* __restrict__ beta) {
    int o = threadIdx.x;
    float mu = g_colsum[o] / (float)N_NODES;
    float var = g_colsumsq[o] / (float)N_NODES - mu * mu;
    float inv = rsqrtf(var + 1e-5f);
    float sc = gamma[o] * inv;
    g_scale[o] = sc;
    g_shift[o] = beta[o] - mu * sc;
}

__global__ __launch_bounds__(256) void k_out(const float* __restrict__ norm,
                                             float* __restrict__ out) {
    int i = blockIdx.x * blockDim.x + threadIdx.x;
    int total = N_NODES * D / 4;
    if (i >= total) return;
    float nm = norm[(i * 4) >> 7];
    float4 a = ((const float4*)g_accum)[i];
    float4 xl = ((const float4*)g_xloop)[i];
    int o = (i * 4) & (D - 1);
    float4 r;
    r.x = fmaxf(0.f, (a.x * nm + xl.x) * g_scale[o + 0] + g_shift[o + 0]);
    r.y = fmaxf(0.f, (a.y * nm + xl.y) * g_scale[o + 1] + g_shift[o + 1]);
    r.z = fmaxf(0.f, (a.z * nm + xl.z) * g_scale[o + 2] + g_shift[o + 2]);
    r.w = fmaxf(0.f, (a.w * nm + xl.w) * g_scale[o + 3] + g_shift[o + 3]);
    ((float4*)out)[i] = r;
}

extern "C" void kernel_launch(void* const* d_in, const int* in_sizes, int n_in,
                              void* d_out, int out_size) {
    const float* x       = (const float*)d_in[0];
    const float* norm    = (const float*)d_in[1];
    const int*   esrc    = (const int*)d_in[2];
    const int*   edst    = (const int*)d_in[3];
    const int*   erel    = (const int*)d_in[4];
    const float* w_loop  = (const float*)d_in[5];
    const float* w_bases = (const float*)d_in[6];
    const float* coef    = (const float*)d_in[7];
    const float* att     = (const float*)d_in[8];
    const float* gamma   = (const float*)d_in[10];
    const float* beta    = (const float*)d_in[11];
    float* out = (float*)d_out;

    cudaFuncSetAttribute(k_gemm_mma, cudaFuncAttributeMaxDynamicSharedMemorySize, SMEM_GEMM);

    k_prep<<<2048, 256>>>(x, w_bases, w_loop);
    k_hist<<<(N_EDGES + 255) / 256, 256>>>(esrc);
    k_scan<<<1, 1024>>>();

    dim3 gg((N_NODES + 127) / 128, 3);
    k_gemm_mma<<<gg, 256, SMEM_GEMM>>>(att);

    k_s2<<<(N_NODES * 32 + 255) / 256, 256>>>(coef);
    k_scatter<<<(N_EDGES + 255) / 256, 256>>>(esrc, edst, erel);
    k_edge2<<<(N_NODES * 32 + 255) / 256, 256>>>(coef);
    k_ft<<<512, 128>>>(norm);
    k_bn<<<1, 128>>>(gamma, beta);
    k_out<<<(N_NODES * D / 4 + 255) / 256, 256>>>(norm, out);
}